// round 2
// baseline (speedup 1.0000x reference)
#include <cuda_runtime.h>
#include <cstdint>

#define BB   16
#define LQ   256
#define LK   4096
#define EE   64
#define DD   32
#define LATD 32
#define HH   4
#define EKH  16

typedef unsigned long long ull;

// ---------------- scratch (device globals; no allocation allowed) ----------
__device__ __align__(16) float g_qproj[BB * LQ * EE];   // 1 MB
__device__ __align__(16) float g_kproj[BB * LK * EE];   // 16 MB
__device__ __align__(16) float g_w[BB * LK * 64];       // 16 MB : [m*v (32) | m (32)]

// ---------------- f32x2 packed-math helpers --------------------------------
__device__ __forceinline__ ull pack2(float lo, float hi) {
    ull r; asm("mov.b64 %0, {%1,%2};" : "=l"(r) : "f"(lo), "f"(hi)); return r;
}
__device__ __forceinline__ void unpack2(ull v, float& lo, float& hi) {
    asm("mov.b64 {%0,%1}, %2;" : "=f"(lo), "=f"(hi) : "l"(v));
}
__device__ __forceinline__ ull ffma2(ull a, ull b, ull c) {
    ull d; asm("fma.rn.f32x2 %0, %1, %2, %3;" : "=l"(d) : "l"(a), "l"(b), "l"(c));
    return d;
}

// ---------------- projection: out[row][e] = in[row][:] @ W + bias ----------
// W is (64 in, 64 out) row-major: W[j*64 + e]. One block = 64 rows.
__global__ void __launch_bounds__(256) proj_kernel(
    const float* __restrict__ in, const float* __restrict__ W,
    const float* __restrict__ bias, int which /*0=q,1=k*/)
{
    __shared__ __align__(16) float Wsh[64 * 64];
    __shared__ __align__(16) float Ish[64 * 68];

    float* out = which ? g_kproj : g_qproj;

    const int t = threadIdx.x;
    const long row0 = (long)blockIdx.x * 64;
    const float4* ing = (const float4*)(in + row0 * 64);
    #pragma unroll
    for (int i = t; i < 1024; i += 256) ((float4*)Wsh)[i] = ((const float4*)W)[i];
    #pragma unroll
    for (int i = t; i < 1024; i += 256) {
        int rr = i >> 4, c = i & 15;
        *(float4*)&Ish[rr * 68 + c * 4] = ing[i];
    }
    __syncthreads();

    const int e0 = (t & 15) * 4;
    const int rb = (t >> 4) * 4;
    float4 bv = *(const float4*)&bias[e0];
    float4 a0 = bv, a1 = bv, a2 = bv, a3 = bv;
    #pragma unroll 8
    for (int j = 0; j < 64; j++) {
        float4 wv = *(const float4*)&Wsh[j * 64 + e0];
        float i0 = Ish[(rb + 0) * 68 + j];
        float i1 = Ish[(rb + 1) * 68 + j];
        float i2 = Ish[(rb + 2) * 68 + j];
        float i3 = Ish[(rb + 3) * 68 + j];
        a0.x += i0 * wv.x; a0.y += i0 * wv.y; a0.z += i0 * wv.z; a0.w += i0 * wv.w;
        a1.x += i1 * wv.x; a1.y += i1 * wv.y; a1.z += i1 * wv.z; a1.w += i1 * wv.w;
        a2.x += i2 * wv.x; a2.y += i2 * wv.y; a2.z += i2 * wv.z; a2.w += i2 * wv.w;
        a3.x += i3 * wv.x; a3.y += i3 * wv.y; a3.z += i3 * wv.z; a3.w += i3 * wv.w;
    }
    *(float4*)&out[(row0 + rb + 0) * 64 + e0] = a0;
    *(float4*)&out[(row0 + rb + 1) * 64 + e0] = a1;
    *(float4*)&out[(row0 + rb + 2) * 64 + e0] = a2;
    *(float4*)&out[(row0 + rb + 3) * 64 + e0] = a3;
}

// ---------------- build W = [m*v | m] ---------------------------------------
__global__ void __launch_bounds__(256) wbuild_kernel(
    const float* __restrict__ v, const int* __restrict__ m)
{
    int i = blockIdx.x * 256 + threadIdx.x;   // over BB*LK*32
    if (i >= BB * LK * 32) return;
    int bk = i >> 5, d = i & 31;
    float mv = (float)m[i];
    g_w[bk * 64 + d]      = mv * v[i];
    g_w[bk * 64 + 32 + d] = mv;
}

// ---------------- main fused attention kernel -------------------------------
// grid (8 qtiles, 16 batches), 256 threads. Streams Lk in chunks of 64.
// Shared layout (floats):
//   Ks  [64*64]  @ 0       (reused as X [32*132] in epilogue, spills into Ws)
//   Ws  [64*64]  @ 4096
//   Es  [4*64*36]@ 8192    (reused as O [4*32*64] in epilogue)
//   Wos [128*32] @ 17408
//   bos [32]     @ 21504
#define SM_KS  0
#define SM_WS  4096
#define SM_ES  8192
#define SM_WOS 17408
#define SM_BOS 21504
#define SM_FLOATS 21536   // 86144 bytes

__global__ void __launch_bounds__(256) attn_main_kernel(
    const float* __restrict__ Wo, const float* __restrict__ bo,
    float* __restrict__ out)
{
    extern __shared__ __align__(16) float sh[];
    float* Ks  = sh + SM_KS;
    float* Ws  = sh + SM_WS;
    float* Es  = sh + SM_ES;
    float* Wos = sh + SM_WOS;
    float* bos = sh + SM_BOS;

    const int t = threadIdx.x;
    const int lane = t & 31;
    const int w = t >> 5;
    const int b = blockIdx.y;
    const int q0 = blockIdx.x * 32;

    // load Wo / bo once
    #pragma unroll
    for (int i = t; i < 1024; i += 256) ((float4*)Wos)[i] = ((const float4*)Wo)[i];
    if (t < 32) bos[t] = bo[t];

    // ---- phase-1 identity: warp w -> head h1, kk-half; lane = q within tile
    const int h1  = w & 3;
    const int kk0 = (w >> 2) * 32;
    ull qp[8];
    {
        const ulonglong2* qv =
            (const ulonglong2*)(g_qproj + ((long)(b * LQ + q0 + lane)) * EE + h1 * EKH);
        #pragma unroll
        for (int i = 0; i < 4; i++) { ulonglong2 v = qv[i]; qp[2*i] = v.x; qp[2*i+1] = v.y; }
    }

    // ---- phase-2 identity: h2, 4 q rows, 8 d columns (4 f32x2 pairs)
    const int h2 = t >> 6;
    const int r  = t & 63;
    const int q2 = (r >> 3) * 4;
    const int d0 = (r & 7) * 8;
    ull acc[4][4];
    #pragma unroll
    for (int i = 0; i < 4; i++)
        #pragma unroll
        for (int j = 0; j < 4; j++) acc[i][j] = 0ull;

    const float* kbase = g_kproj + (long)b * LK * EE;
    const float* wbase = g_w     + (long)b * LK * 64;
    const float* ebase = Es + h2 * 64 * 36 + q2;
    const float* wsd   = Ws + d0;
    const float* krow  = Ks + h1 * EKH;

    for (int c = 0; c < 64; ++c) {
        __syncthreads();   // previous phase-2 done with Ws/Es
        const float4* kg = (const float4*)(kbase + c * 64 * 64);
        const float4* wg = (const float4*)(wbase + c * 64 * 64);
        #pragma unroll
        for (int i = t; i < 1024; i += 256) {
            ((float4*)Ks)[i] = kg[i];
            ((float4*)Ws)[i] = wg[i];
        }
        __syncthreads();

        // phase 1: e = exp(q.k / 4); K reads warp-uniform (broadcast)
        #pragma unroll 2
        for (int i = 0; i < 32; i++) {
            int kk = kk0 + i;
            const ulonglong2* kv = (const ulonglong2*)(krow + kk * 64);
            ulonglong2 v0 = kv[0], v1 = kv[1], v2 = kv[2], v3 = kv[3];
            ull a0 = ffma2(qp[0], v0.x, 0ull);
            ull a1 = ffma2(qp[1], v0.y, 0ull);
            a0 = ffma2(qp[2], v1.x, a0);  a1 = ffma2(qp[3], v1.y, a1);
            a0 = ffma2(qp[4], v2.x, a0);  a1 = ffma2(qp[5], v2.y, a1);
            a0 = ffma2(qp[6], v3.x, a0);  a1 = ffma2(qp[7], v3.y, a1);
            float s0, s1, s2, s3; unpack2(a0, s0, s1); unpack2(a1, s2, s3);
            float s = (s0 + s2) + (s1 + s3);
            Es[(h1 * 64 + kk) * 36 + lane] = __expf(s * 0.25f);
        }
        __syncthreads();

        // phase 2: acc[q][d-pair] += e[q] * W[kk][d]
        #pragma unroll 4
        for (int kk = 0; kk < 64; kk++) {
            float4 ev = *(const float4*)(ebase + kk * 36);
            ulonglong2 u0 = *(const ulonglong2*)(wsd + kk * 64);
            ulonglong2 u1 = *(const ulonglong2*)(wsd + kk * 64 + 4);
            ull ee0 = pack2(ev.x, ev.x), ee1 = pack2(ev.y, ev.y);
            ull ee2 = pack2(ev.z, ev.z), ee3 = pack2(ev.w, ev.w);
            acc[0][0] = ffma2(ee0, u0.x, acc[0][0]);
            acc[0][1] = ffma2(ee0, u0.y, acc[0][1]);
            acc[0][2] = ffma2(ee0, u1.x, acc[0][2]);
            acc[0][3] = ffma2(ee0, u1.y, acc[0][3]);
            acc[1][0] = ffma2(ee1, u0.x, acc[1][0]);
            acc[1][1] = ffma2(ee1, u0.y, acc[1][1]);
            acc[1][2] = ffma2(ee1, u1.x, acc[1][2]);
            acc[1][3] = ffma2(ee1, u1.y, acc[1][3]);
            acc[2][0] = ffma2(ee2, u0.x, acc[2][0]);
            acc[2][1] = ffma2(ee2, u0.y, acc[2][1]);
            acc[2][2] = ffma2(ee2, u1.x, acc[2][2]);
            acc[2][3] = ffma2(ee2, u1.y, acc[2][3]);
            acc[3][0] = ffma2(ee3, u0.x, acc[3][0]);
            acc[3][1] = ffma2(ee3, u0.y, acc[3][1]);
            acc[3][2] = ffma2(ee3, u1.x, acc[3][2]);
            acc[3][3] = ffma2(ee3, u1.y, acc[3][3]);
        }
    }

    // ---- epilogue: O = [num|den] -> X = num/den -> out = X @ Wo + bo
    __syncthreads();                 // everyone done reading Es
    float* O = Es;                   // O[h][q][64]
    #pragma unroll
    for (int qi = 0; qi < 4; qi++) {
        #pragma unroll
        for (int dp = 0; dp < 4; dp++) {
            float lo, hi; unpack2(acc[qi][dp], lo, hi);
            int base = (h2 * 32 + q2 + qi) * 64 + d0 + 2 * dp;
            O[base]     = lo;
            O[base + 1] = hi;
        }
    }
    __syncthreads();

    float* X = Ks;                   // X[32][132] (spills into Ws region; both dead)
    for (int i = t; i < 32 * 128; i += 256) {
        int q = i >> 7, j = i & 127;
        int h = j >> 5, d = j & 31;
        float num = O[(h * 32 + q) * 64 + d];
        float den = O[(h * 32 + q) * 64 + 32 + d];
        X[q * 132 + j] = __fdividef(num, den);
    }
    __syncthreads();

    const int qo   = t >> 3;
    const int lat0 = (t & 7) * 4;
    float4 o;
    o.x = bos[lat0]; o.y = bos[lat0 + 1]; o.z = bos[lat0 + 2]; o.w = bos[lat0 + 3];
    #pragma unroll 16
    for (int j = 0; j < 128; j++) {
        float xv = X[qo * 132 + j];
        float4 wv = *(const float4*)&Wos[j * 32 + lat0];
        o.x += xv * wv.x; o.y += xv * wv.y; o.z += xv * wv.z; o.w += xv * wv.w;
    }
    *(float4*)&out[((long)(b * LQ + q0 + qo)) * LATD + lat0] = o;
}

// ---------------- launch ----------------------------------------------------
extern "C" void kernel_launch(void* const* d_in, const int* in_sizes, int n_in,
                              void* d_out, int out_size)
{
    const float* query = (const float*)d_in[0];
    const float* key   = (const float*)d_in[1];
    const float* value = (const float*)d_in[2];
    const int*   mask  = (const int*)  d_in[3];
    const float* Wq    = (const float*)d_in[4];
    const float* bq    = (const float*)d_in[5];
    const float* Wk    = (const float*)d_in[6];
    const float* bk    = (const float*)d_in[7];
    const float* Wo    = (const float*)d_in[8];
    const float* bo    = (const float*)d_in[9];
    float* out = (float*)d_out;
    (void)in_sizes; (void)n_in; (void)out_size;

    cudaFuncSetAttribute(attn_main_kernel,
                         cudaFuncAttributeMaxDynamicSharedMemorySize,
                         SM_FLOATS * (int)sizeof(float));

    // projections
    proj_kernel<<<(BB * LQ) / 64, 256>>>(query, Wq, bq, 0);
    proj_kernel<<<(BB * LK) / 64, 256>>>(key,   Wk, bk, 1);
    // W = [m*v | m]
    wbuild_kernel<<<(BB * LK * 32 + 255) / 256, 256>>>(value, mask);
    // main fused attention + output projection
    dim3 grid(LQ / 32, BB);
    attn_main_kernel<<<grid, 256, SM_FLOATS * (int)sizeof(float)>>>(Wo, bo, out);
}

// round 4
// speedup vs baseline: 7.7964x; 7.7964x over previous
#include <cuda_runtime.h>
#include <cuda_fp16.h>
#include <cstdint>

#define BB 16
#define LQ 256
#define LK 4096

// ---------------- device scratch (no allocation allowed) --------------------
__device__ __align__(16) __half g_qh[BB * LQ * 64];          // Q proj, f16, pre-scaled
__device__ __align__(16) __half g_kh[(long)BB * LK * 64];    // K proj, f16
__device__ __align__(16) __half g_wth[(long)BB * 64 * LK];   // Wt[b][d0..63][kk]: [m*v | m]

// ---------------- helpers ----------------------------------------------------
__device__ __forceinline__ uint32_t smem_u32(const void* p) {
    uint32_t a;
    asm("{ .reg .u64 t; cvta.to.shared.u64 t, %1; cvt.u32.u64 %0, t; }" : "=r"(a) : "l"(p));
    return a;
}
__device__ __forceinline__ uint32_t f16x2_of(float lo, float hi) {
    uint32_t r; asm("cvt.rn.f16x2.f32 %0, %1, %2;" : "=r"(r) : "f"(hi), "f"(lo)); return r;
}
__device__ __forceinline__ uint32_t ex2x2(uint32_t a) {
    uint32_t r; asm("ex2.approx.f16x2 %0, %1;" : "=r"(r) : "r"(a)); return r;
}
__device__ __forceinline__ void cp16(uint32_t dst, const void* src) {
    asm volatile("cp.async.ca.shared.global [%0], [%1], 16;" :: "r"(dst), "l"(src));
}
#define CP_COMMIT() asm volatile("cp.async.commit_group;" ::: "memory")
#define CP_WAIT(n)  asm volatile("cp.async.wait_group %0;" :: "n"(n) : "memory")

__device__ __forceinline__ void ldsm_x2(uint32_t& r0, uint32_t& r1, uint32_t a) {
    asm volatile("ldmatrix.sync.aligned.m8n8.x2.shared.b16 {%0,%1}, [%2];"
                 : "=r"(r0), "=r"(r1) : "r"(a));
}
__device__ __forceinline__ void ldsm_x4(uint32_t* r, uint32_t a) {
    asm volatile("ldmatrix.sync.aligned.m8n8.x4.shared.b16 {%0,%1,%2,%3}, [%4];"
                 : "=r"(r[0]), "=r"(r[1]), "=r"(r[2]), "=r"(r[3]) : "r"(a));
}
// D = A*B + C   (m16n8k16, f16 in, f32 acc), in-place on d
__device__ __forceinline__ void mma_acc(float* d, const uint32_t* a, const uint32_t* b) {
    asm volatile("mma.sync.aligned.m16n8k16.row.col.f32.f16.f16.f32 "
        "{%0,%1,%2,%3}, {%4,%5,%6,%7}, {%8,%9}, {%0,%1,%2,%3};"
        : "+f"(d[0]), "+f"(d[1]), "+f"(d[2]), "+f"(d[3])
        : "r"(a[0]), "r"(a[1]), "r"(a[2]), "r"(a[3]), "r"(b[0]), "r"(b[1]));
}
__device__ __forceinline__ void mma_zro(float* d, const uint32_t* a, const uint32_t* b) {
    asm volatile("mma.sync.aligned.m16n8k16.row.col.f32.f16.f16.f32 "
        "{%0,%1,%2,%3}, {%4,%5,%6,%7}, {%8,%9}, {%10,%10,%10,%10};"
        : "=f"(d[0]), "=f"(d[1]), "=f"(d[2]), "=f"(d[3])
        : "r"(a[0]), "r"(a[1]), "r"(a[2]), "r"(a[3]), "r"(b[0]), "r"(b[1]), "f"(0.0f));
}

// ---------------- projection: g_{q,k}h = f16((in @ W + bias) * scale) -------
__global__ void __launch_bounds__(256) proj_kernel(
    const float* __restrict__ in, const float* __restrict__ W,
    const float* __restrict__ bias, int which, float scale)
{
    __shared__ __align__(16) float Wsh[64 * 64];
    __shared__ __align__(16) float Ish[64 * 68];
    __half* out = which ? g_kh : g_qh;
    const int t = threadIdx.x;
    const long row0 = (long)blockIdx.x * 64;
    const float4* ing = (const float4*)(in + row0 * 64);
    #pragma unroll
    for (int i = t; i < 1024; i += 256) ((float4*)Wsh)[i] = ((const float4*)W)[i];
    #pragma unroll
    for (int i = t; i < 1024; i += 256) {
        int rr = i >> 4, c = i & 15;
        *(float4*)&Ish[rr * 68 + c * 4] = ing[i];
    }
    __syncthreads();
    const int e0 = (t & 15) * 4;
    const int rb = (t >> 4) * 4;
    float4 bv = *(const float4*)&bias[e0];
    float4 a0 = bv, a1 = bv, a2 = bv, a3 = bv;
    #pragma unroll 8
    for (int j = 0; j < 64; j++) {
        float4 wv = *(const float4*)&Wsh[j * 64 + e0];
        float i0 = Ish[(rb + 0) * 68 + j];
        float i1 = Ish[(rb + 1) * 68 + j];
        float i2 = Ish[(rb + 2) * 68 + j];
        float i3 = Ish[(rb + 3) * 68 + j];
        a0.x += i0 * wv.x; a0.y += i0 * wv.y; a0.z += i0 * wv.z; a0.w += i0 * wv.w;
        a1.x += i1 * wv.x; a1.y += i1 * wv.y; a1.z += i1 * wv.z; a1.w += i1 * wv.w;
        a2.x += i2 * wv.x; a2.y += i2 * wv.y; a2.z += i2 * wv.z; a2.w += i2 * wv.w;
        a3.x += i3 * wv.x; a3.y += i3 * wv.y; a3.z += i3 * wv.z; a3.w += i3 * wv.w;
    }
    float4 aa[4] = {a0, a1, a2, a3};
    #pragma unroll
    for (int r = 0; r < 4; r++) {
        uint2 u;
        u.x = f16x2_of(aa[r].x * scale, aa[r].y * scale);
        u.y = f16x2_of(aa[r].z * scale, aa[r].w * scale);
        *(uint2*)&out[(row0 + rb + r) * 64 + e0] = u;
    }
}

// ---------------- Wt build: g_wth[b][d][kk] = [m*v | m] (f16) ----------------
__global__ void __launch_bounds__(256) wt_kernel(
    const float* __restrict__ v, const int* __restrict__ m)
{
    __shared__ __half Wsm[64][144];
    const int t = threadIdx.x;
    const int b = blockIdx.x >> 5, kt = blockIdx.x & 31;
    const long base = ((long)b * LK + kt * 128) * 32;
    for (int i = t; i < 4096; i += 256) {
        int kk = i >> 5, d = i & 31;
        float mv = (float)m[base + i];
        float vv = v[base + i];
        Wsm[d][kk]      = __float2half(mv * vv);
        Wsm[d + 32][kk] = __float2half(mv);
    }
    __syncthreads();
    for (int i = t; i < 1024; i += 256) {
        int row = i >> 4, c = i & 15;
        *(uint4*)(g_wth + ((long)b * 64 + row) * LK + kt * 128 + c * 8) =
            *(uint4*)&Wsm[row][c * 8];
    }
}

// ---------------- main fused attention (HMMA + f16x2 ex2) --------------------
// grid (8 qt, 16 b), 128 threads (4 warps = 4 heads). 32 q-rows per CTA.
// SMEM: Q tile 4KB @0; chunk buffers p in {0,1}: K 8KB @4096+p*16384,
//       W 8KB @12288+p*16384. Epilogue X[32][132] f32 reuses @4096.
__global__ void __launch_bounds__(128) attn_kernel(
    const float* __restrict__ Wo, const float* __restrict__ bo,
    float* __restrict__ out)
{
    __shared__ __align__(1024) char sm[36864];
    const uint32_t sb = smem_u32(sm);

    const int t = threadIdx.x, l = t & 31, h = t >> 5;
    const int qt = blockIdx.x, b = blockIdx.y;

    const char*   qg = (const char*)(g_qh + ((long)(b * LQ + qt * 32)) * 64);
    const __half* kg = g_kh  + (long)b * LK * 64;
    const __half* wg = g_wth + (long)b * 64 * LK;

    // Q tile (4KB contiguous) + chunk 0, one cp.async group
    #pragma unroll
    for (int i = t; i < 256; i += 128) {
        uint32_t off = i * 16;
        cp16(sb + (off ^ ((off >> 3) & 0x70)), qg + off);
    }
    {
        const uint32_t KB = sb + 4096, WB = sb + 12288;
        const char* ks = (const char*)kg;   // chunk 0
        #pragma unroll
        for (int i = t; i < 512; i += 128) {
            uint32_t off = i * 16, sw = off ^ ((off >> 3) & 0x70);
            cp16(KB + sw, ks + off);
            cp16(WB + sw, (const char*)(wg + (long)(i >> 3) * LK) + (i & 7) * 16);
        }
    }
    CP_COMMIT();

    // per-lane ldmatrix address pieces (swizzle = off ^ ((row&7)<<4))
    const int li = l & 7, sel = (l >> 3) & 1;
    const uint32_t rowb = (uint32_t)li * 128;
    const uint32_t kLane = rowb + (((uint32_t)(h * 32 + sel * 16)) ^ ((uint32_t)li << 4));
    uint32_t wLane[4];
    #pragma unroll
    for (int j = 0; j < 4; j++)
        wLane[j] = rowb + (((uint32_t)(j * 32 + sel * 16)) ^ ((uint32_t)li << 4));

    CP_WAIT(0);
    __syncthreads();

    // A frags for Q (constant over chunks): 2 m-tiles x 4 regs
    uint32_t aq[2][4];
    {
        const int quad = l >> 3;
        const uint32_t arow = (uint32_t)(((quad & 1) * 8 + li)) * 128;
        const uint32_t acol = ((uint32_t)(h * 32 + (quad >> 1) * 16)) ^ ((uint32_t)li << 4);
        ldsm_x4(aq[0], sb + 0    + arow + acol);
        ldsm_x4(aq[1], sb + 2048 + arow + acol);
    }

    float O[2][8][4];
    #pragma unroll
    for (int mt = 0; mt < 2; mt++)
        #pragma unroll
        for (int nt = 0; nt < 8; nt++)
            #pragma unroll
            for (int i = 0; i < 4; i++) O[mt][nt][i] = 0.0f;

    for (int c = 0; c < 64; c++) {
        const int p = c & 1;
        if (c < 63) {   // prefetch chunk c+1 into buffer p^1
            const uint32_t KB = sb + 4096 + (p ^ 1) * 16384, WB = KB + 8192;
            const char* ks = (const char*)(kg + (long)(c + 1) * 64 * 64);
            const int kk0 = (c + 1) * 64;
            #pragma unroll
            for (int i = t; i < 512; i += 128) {
                uint32_t off = i * 16, sw = off ^ ((off >> 3) & 0x70);
                cp16(KB + sw, ks + off);
                cp16(WB + sw, (const char*)(wg + (long)(i >> 3) * LK + kk0) + (i & 7) * 16);
            }
            CP_COMMIT();
            CP_WAIT(1);
        } else {
            CP_WAIT(0);
        }
        __syncthreads();

        const uint32_t KBp = sb + 4096 + p * 16384, WBp = KBp + 8192;

        // GEMM1 + exp: S = Q.K^T (scaled to log2 domain already), E = 2^S (f16)
        uint32_t E[2][4][4];
        #pragma unroll
        for (int j = 0; j < 4; j++) {
            uint32_t b0[2], b1[2];
            ldsm_x2(b0[0], b0[1], KBp + (uint32_t)(2 * j)     * 1024 + kLane);
            ldsm_x2(b1[0], b1[1], KBp + (uint32_t)(2 * j + 1) * 1024 + kLane);
            #pragma unroll
            for (int mt = 0; mt < 2; mt++) {
                float s0[4], s1[4];
                mma_zro(s0, aq[mt], b0);
                mma_zro(s1, aq[mt], b1);
                E[mt][j][0] = ex2x2(f16x2_of(s0[0], s0[1]));
                E[mt][j][1] = ex2x2(f16x2_of(s0[2], s0[3]));
                E[mt][j][2] = ex2x2(f16x2_of(s1[0], s1[1]));
                E[mt][j][3] = ex2x2(f16x2_of(s1[2], s1[3]));
            }
        }

        // GEMM2: O += E . Wt^T   (n = 64 = [num(32) | den(32)])
        #pragma unroll
        for (int j = 0; j < 4; j++) {
            #pragma unroll
            for (int nt = 0; nt < 8; nt++) {
                uint32_t bw[2];
                ldsm_x2(bw[0], bw[1], WBp + (uint32_t)nt * 1024 + wLane[j]);
                mma_acc(O[0][nt], E[0][j], bw);
                mma_acc(O[1][nt], E[1][j], bw);
            }
        }
        __syncthreads();   // chunk buffers free for next prefetch
    }

    // ---- epilogue: X = num/den -> out = X @ Wo + bo --------------------------
    float* Xs = (float*)(sm + 4096);   // [32][132]
    #pragma unroll
    for (int mt = 0; mt < 2; mt++)
        #pragma unroll
        for (int nt = 0; nt < 4; nt++)
            #pragma unroll
            for (int i = 0; i < 4; i++) {
                float x = __fdividef(O[mt][nt][i], O[mt][nt + 4][i]);
                int q = mt * 16 + (l >> 2) + ((i >> 1) & 1) * 8;
                int col = h * 32 + nt * 8 + 2 * (l & 3) + (i & 1);
                Xs[q * 132 + col] = x;
            }
    __syncthreads();

    const int q = t >> 2, lat0 = (t & 3) * 8;
    float acc[8];
    #pragma unroll
    for (int i = 0; i < 8; i++) acc[i] = bo[lat0 + i];
    #pragma unroll 8
    for (int j = 0; j < 128; j++) {
        float xv = Xs[q * 132 + j];
        float4 w0 = *(const float4*)&Wo[j * 32 + lat0];
        float4 w1 = *(const float4*)&Wo[j * 32 + lat0 + 4];
        acc[0] += xv * w0.x; acc[1] += xv * w0.y; acc[2] += xv * w0.z; acc[3] += xv * w0.w;
        acc[4] += xv * w1.x; acc[5] += xv * w1.y; acc[6] += xv * w1.z; acc[7] += xv * w1.w;
    }
    float* op = out + ((long)(b * LQ + qt * 32 + q)) * 32 + lat0;
    *(float4*)op       = make_float4(acc[0], acc[1], acc[2], acc[3]);
    *(float4*)(op + 4) = make_float4(acc[4], acc[5], acc[6], acc[7]);
}

// ---------------- launch ------------------------------------------------------
extern "C" void kernel_launch(void* const* d_in, const int* in_sizes, int n_in,
                              void* d_out, int out_size)
{
    const float* query = (const float*)d_in[0];
    const float* key   = (const float*)d_in[1];
    const float* value = (const float*)d_in[2];
    const int*   mask  = (const int*)  d_in[3];
    const float* Wq    = (const float*)d_in[4];
    const float* bq    = (const float*)d_in[5];
    const float* Wk    = (const float*)d_in[6];
    const float* bk    = (const float*)d_in[7];
    const float* Wo    = (const float*)d_in[8];
    const float* bo    = (const float*)d_in[9];
    float* out = (float*)d_out;
    (void)in_sizes; (void)n_in; (void)out_size;

    // Q pre-scaled by 0.25*log2(e): GEMM1 output is the exp2 exponent directly
    proj_kernel<<<(BB * LQ) / 64, 256>>>(query, Wq, bq, 0, 0.36067376022224085f);
    proj_kernel<<<(BB * LK) / 64, 256>>>(key,   Wk, bk, 1, 1.0f);
    wt_kernel<<<BB * 32, 256>>>(value, mask);

    dim3 grid(LQ / 32, BB);
    attn_kernel<<<grid, 128>>>(Wo, bo, out);
}

// round 5
// speedup vs baseline: 8.2820x; 1.0623x over previous
#include <cuda_runtime.h>
#include <cuda_fp16.h>
#include <cstdint>

#define BB 16
#define LQ 256
#define LK 4096

typedef unsigned long long ull;

// ---------------- device scratch (no allocation allowed) --------------------
__device__ __align__(16) __half g_qh [BB * LQ * 64];         // Q proj hi, pre-scaled
__device__ __align__(16) __half g_qlo[BB * LQ * 64];         // Q proj lo residual
__device__ __align__(16) __half g_kh [(long)BB * LK * 64];   // K proj
__device__ __align__(16) __half g_wth[(long)BB * 64 * LK];   // Wt[b][d][kk] = [m*v | m]

// ---------------- helpers ----------------------------------------------------
__device__ __forceinline__ uint32_t smem_u32(const void* p) {
    uint32_t a;
    asm("{ .reg .u64 t; cvta.to.shared.u64 t, %1; cvt.u32.u64 %0, t; }" : "=r"(a) : "l"(p));
    return a;
}
__device__ __forceinline__ uint32_t f16x2_of(float lo, float hi) {
    uint32_t r; asm("cvt.rn.f16x2.f32 %0, %1, %2;" : "=r"(r) : "f"(hi), "f"(lo)); return r;
}
__device__ __forceinline__ uint32_t ex2x2(uint32_t a) {
    uint32_t r; asm("ex2.approx.f16x2 %0, %1;" : "=r"(r) : "r"(a)); return r;
}
__device__ __forceinline__ ull pack2(float lo, float hi) {
    ull r; asm("mov.b64 %0, {%1,%2};" : "=l"(r) : "f"(lo), "f"(hi)); return r;
}
__device__ __forceinline__ void unpack2(ull v, float& lo, float& hi) {
    asm("mov.b64 {%0,%1}, %2;" : "=f"(lo), "=f"(hi) : "l"(v));
}
__device__ __forceinline__ ull ffma2(ull a, ull b, ull c) {
    ull d; asm("fma.rn.f32x2 %0, %1, %2, %3;" : "=l"(d) : "l"(a), "l"(b), "l"(c));
    return d;
}
__device__ __forceinline__ void cp16(uint32_t dst, const void* src) {
    asm volatile("cp.async.ca.shared.global [%0], [%1], 16;" :: "r"(dst), "l"(src));
}
#define CP_COMMIT() asm volatile("cp.async.commit_group;" ::: "memory")
#define CP_WAIT(n)  asm volatile("cp.async.wait_group %0;" :: "n"(n) : "memory")

__device__ __forceinline__ void ldsm_x2(uint32_t& r0, uint32_t& r1, uint32_t a) {
    asm volatile("ldmatrix.sync.aligned.m8n8.x2.shared.b16 {%0,%1}, [%2];"
                 : "=r"(r0), "=r"(r1) : "r"(a));
}
__device__ __forceinline__ void ldsm_x4(uint32_t* r, uint32_t a) {
    asm volatile("ldmatrix.sync.aligned.m8n8.x4.shared.b16 {%0,%1,%2,%3}, [%4];"
                 : "=r"(r[0]), "=r"(r[1]), "=r"(r[2]), "=r"(r[3]) : "r"(a));
}
__device__ __forceinline__ void mma_acc(float* d, const uint32_t* a, const uint32_t* b) {
    asm volatile("mma.sync.aligned.m16n8k16.row.col.f32.f16.f16.f32 "
        "{%0,%1,%2,%3}, {%4,%5,%6,%7}, {%8,%9}, {%0,%1,%2,%3};"
        : "+f"(d[0]), "+f"(d[1]), "+f"(d[2]), "+f"(d[3])
        : "r"(a[0]), "r"(a[1]), "r"(a[2]), "r"(a[3]), "r"(b[0]), "r"(b[1]));
}
__device__ __forceinline__ void mma_zro(float* d, const uint32_t* a, const uint32_t* b) {
    asm volatile("mma.sync.aligned.m16n8k16.row.col.f32.f16.f16.f32 "
        "{%0,%1,%2,%3}, {%4,%5,%6,%7}, {%8,%9}, {%10,%10,%10,%10};"
        : "=f"(d[0]), "=f"(d[1]), "=f"(d[2]), "=f"(d[3])
        : "r"(a[0]), "r"(a[1]), "r"(a[2]), "r"(a[3]), "r"(b[0]), "r"(b[1]), "f"(0.0f));
}

#define QSCALE 0.36067376022224085f   // 0.25 * log2(e)

// ---------------- fused prep: proj-q(hi/lo) | proj-k | Wt build --------------
// grid 1600: [0,64) proj q, [64,1088) proj k, [1088,1600) wt
__global__ void __launch_bounds__(256) prep_kernel(
    const float* __restrict__ qin, const float* __restrict__ kin,
    const float* __restrict__ v, const int* __restrict__ m,
    const float* __restrict__ Wq, const float* __restrict__ bq,
    const float* __restrict__ Wk, const float* __restrict__ bk)
{
    __shared__ __align__(16) float Wsh[64 * 64];
    __shared__ __align__(16) float Ish[64 * 68];
    const int bid = blockIdx.x, t = threadIdx.x;

    if (bid < 1088) {
        const int isq = (bid < 64);
        const float* in   = isq ? qin : kin;
        const float* W    = isq ? Wq : Wk;
        const float* bias = isq ? bq : bk;
        const long row0 = (long)(isq ? bid : bid - 64) * 64;
        const float4* ing = (const float4*)(in + row0 * 64);
        #pragma unroll
        for (int i = t; i < 1024; i += 256) ((float4*)Wsh)[i] = ((const float4*)W)[i];
        #pragma unroll
        for (int i = t; i < 1024; i += 256) {
            int rr = i >> 4, c = i & 15;
            *(float4*)&Ish[rr * 68 + c * 4] = ing[i];
        }
        __syncthreads();

        const int e0 = (t & 15) * 4;
        const int rb = (t >> 4) * 4;
        float4 bv = *(const float4*)&bias[e0];
        ull a01 = pack2(bv.x, bv.y), a23 = pack2(bv.z, bv.w);
        ull acc[4][2];
        #pragma unroll
        for (int r = 0; r < 4; r++) { acc[r][0] = a01; acc[r][1] = a23; }
        #pragma unroll 8
        for (int j = 0; j < 64; j++) {
            ulonglong2 w = *(const ulonglong2*)&Wsh[j * 64 + e0];
            #pragma unroll
            for (int r = 0; r < 4; r++) {
                float iv = Ish[(rb + r) * 68 + j];
                ull dv = pack2(iv, iv);
                acc[r][0] = ffma2(dv, w.x, acc[r][0]);
                acc[r][1] = ffma2(dv, w.y, acc[r][1]);
            }
        }
        #pragma unroll
        for (int r = 0; r < 4; r++) {
            float v0, v1, v2, v3;
            unpack2(acc[r][0], v0, v1);
            unpack2(acc[r][1], v2, v3);
            long o = (row0 + rb + r) * 64 + e0;
            if (isq) {
                v0 *= QSCALE; v1 *= QSCALE; v2 *= QSCALE; v3 *= QSCALE;
                uint2 hi;
                hi.x = f16x2_of(v0, v1); hi.y = f16x2_of(v2, v3);
                __half2 h0 = *(__half2*)&hi.x, h1 = *(__half2*)&hi.y;
                uint2 lo;
                lo.x = f16x2_of(v0 - __half2float(h0.x), v1 - __half2float(h0.y));
                lo.y = f16x2_of(v2 - __half2float(h1.x), v3 - __half2float(h1.y));
                *(uint2*)&g_qh[o]  = hi;
                *(uint2*)&g_qlo[o] = lo;
            } else {
                uint2 u;
                u.x = f16x2_of(v0, v1); u.y = f16x2_of(v2, v3);
                *(uint2*)&g_kh[o] = u;
            }
        }
    } else {
        // Wt build: g_wth[b][d][kk] = [m*v | m] (f16), via SMEM transpose
        __half* Wsm = (__half*)Wsh;           // [64][144] = 18KB, fits region
        const int id = bid - 1088;
        const int b = id >> 5, kt = id & 31;
        const long base = ((long)b * LK + kt * 128) * 32;
        for (int i = t; i < 4096; i += 256) {
            int kk = i >> 5, d = i & 31;
            float mv = (float)m[base + i];
            float vv = v[base + i];
            Wsm[d * 144 + kk]        = __float2half(mv * vv);
            Wsm[(d + 32) * 144 + kk] = __float2half(mv);
        }
        __syncthreads();
        for (int i = t; i < 1024; i += 256) {
            int row = i >> 4, c = i & 15;
            *(uint4*)(g_wth + ((long)b * 64 + row) * LK + kt * 128 + c * 8) =
                *(uint4*)&Wsm[row * 144 + c * 8];
        }
    }
}

// ---------------- main fused attention (HMMA + f16x2 ex2) --------------------
// grid (8 qt, 16 b), 256 threads = 8 warps: warp = (head h = w&3, kk-half s = w>>2).
// SMEM: Qhi 4KB @0, Qlo 4KB @4096; chunk buffers p: K @8192+p*16384, W @+8192.
// Epilogue reuses buffer region for O staging then X.
__global__ void __launch_bounds__(256) attn_kernel(
    const float* __restrict__ Wo, const float* __restrict__ bo,
    float* __restrict__ out)
{
    __shared__ __align__(1024) char sm[40960];
    const uint32_t sb = smem_u32(sm);

    const int t = threadIdx.x, l = t & 31, w = t >> 5;
    const int h = w & 3, s = w >> 2;
    const int qt = blockIdx.x, b = blockIdx.y;

    const char*   qgh = (const char*)(g_qh  + ((long)(b * LQ + qt * 32)) * 64);
    const char*   qgl = (const char*)(g_qlo + ((long)(b * LQ + qt * 32)) * 64);
    const __half* kg  = g_kh  + (long)b * LK * 64;
    const __half* wg  = g_wth + (long)b * 64 * LK;

    // Q hi/lo tiles + chunk 0, one cp.async group
    #pragma unroll
    for (int i = t; i < 512; i += 256) {
        uint32_t off = (i & 255) * 16, sw = off ^ ((off >> 3) & 0x70);
        cp16(sb + (i < 256 ? 0u : 4096u) + sw, (i < 256 ? qgh : qgl) + off);
    }
    {
        const uint32_t KB = sb + 8192, WB = sb + 16384;
        const char* ks = (const char*)kg;
        #pragma unroll
        for (int i = t; i < 512; i += 256) {
            uint32_t off = i * 16, sw = off ^ ((off >> 3) & 0x70);
            cp16(KB + sw, ks + off);
            cp16(WB + sw, (const char*)(wg + (long)(i >> 3) * LK) + (i & 7) * 16);
        }
    }
    CP_COMMIT();

    // per-lane ldmatrix address pieces
    const int li = l & 7, sel = (l >> 3) & 1;
    const uint32_t rowb = (uint32_t)li * 128;
    const uint32_t kLane = rowb + (((uint32_t)(h * 32 + sel * 16)) ^ ((uint32_t)li << 4));
    uint32_t wLane[2];
    #pragma unroll
    for (int j = 0; j < 2; j++)
        wLane[j] = rowb + (((uint32_t)(s * 64 + j * 32 + sel * 16)) ^ ((uint32_t)li << 4));

    CP_WAIT(0);
    __syncthreads();

    // Q A-frags (hi & lo), constant over chunks
    uint32_t aqh[2][4], aql[2][4];
    {
        const int quad = l >> 3;
        const uint32_t arow = (uint32_t)((quad & 1) * 8 + li) * 128;
        const uint32_t acol = ((uint32_t)(h * 32 + (quad >> 1) * 16)) ^ ((uint32_t)li << 4);
        ldsm_x4(aqh[0], sb + 0    + arow + acol);
        ldsm_x4(aqh[1], sb + 2048 + arow + acol);
        ldsm_x4(aql[0], sb + 4096 + arow + acol);
        ldsm_x4(aql[1], sb + 6144 + arow + acol);
    }

    float O[2][8][4];
    #pragma unroll
    for (int mt = 0; mt < 2; mt++)
        #pragma unroll
        for (int nt = 0; nt < 8; nt++)
            #pragma unroll
            for (int i = 0; i < 4; i++) O[mt][nt][i] = 0.0f;

    for (int c = 0; c < 64; c++) {
        const int p = c & 1;
        if (c < 63) {   // prefetch chunk c+1 into buffer p^1
            const uint32_t KB = sb + 8192 + (p ^ 1) * 16384, WB = KB + 8192;
            const char* ks = (const char*)(kg + (long)(c + 1) * 64 * 64);
            const int kk0 = (c + 1) * 64;
            #pragma unroll
            for (int i = t; i < 512; i += 256) {
                uint32_t off = i * 16, sw = off ^ ((off >> 3) & 0x70);
                cp16(KB + sw, ks + off);
                cp16(WB + sw, (const char*)(wg + (long)(i >> 3) * LK + kk0) + (i & 7) * 16);
            }
            CP_COMMIT();
            CP_WAIT(1);
        } else {
            CP_WAIT(0);
        }
        __syncthreads();

        const uint32_t KBp = sb + 8192 + p * 16384, WBp = KBp + 8192;

        // GEMM1 (q hi/lo split) + exp: warp covers kk [s*32, s*32+32)
        uint32_t E[2][2][4];
        #pragma unroll
        for (int j = 0; j < 2; j++) {
            uint32_t b0[2], b1[2];
            const uint32_t ka = KBp + (uint32_t)s * 4096 + (uint32_t)(2 * j) * 1024 + kLane;
            ldsm_x2(b0[0], b0[1], ka);
            ldsm_x2(b1[0], b1[1], ka + 1024);
            #pragma unroll
            for (int mt = 0; mt < 2; mt++) {
                float s0[4], s1[4];
                mma_zro(s0, aqh[mt], b0);
                mma_acc(s0, aql[mt], b0);
                mma_zro(s1, aqh[mt], b1);
                mma_acc(s1, aql[mt], b1);
                E[mt][j][0] = ex2x2(f16x2_of(s0[0], s0[1]));
                E[mt][j][1] = ex2x2(f16x2_of(s0[2], s0[3]));
                E[mt][j][2] = ex2x2(f16x2_of(s1[0], s1[1]));
                E[mt][j][3] = ex2x2(f16x2_of(s1[2], s1[3]));
            }
        }

        // GEMM2: O += E . Wt^T over this warp's 32 kk
        #pragma unroll
        for (int j = 0; j < 2; j++) {
            #pragma unroll
            for (int nt = 0; nt < 8; nt++) {
                uint32_t bw[2];
                ldsm_x2(bw[0], bw[1], WBp + (uint32_t)nt * 1024 + wLane[j]);
                mma_acc(O[0][nt], E[0][j], bw);
                mma_acc(O[1][nt], E[1][j], bw);
            }
        }
        __syncthreads();
    }

    // ---- epilogue: reduce kk-halves, X = num/den, out = X @ Wo + bo ---------
    float* stage = (float*)(sm + 8192);   // 4 heads x 32q x 64col (xor-swizzled)
    if (s == 1) {
        #pragma unroll
        for (int mt = 0; mt < 2; mt++)
            #pragma unroll
            for (int nt = 0; nt < 8; nt++)
                #pragma unroll
                for (int i = 0; i < 4; i++) {
                    int q = mt * 16 + (l >> 2) + ((i >> 1) & 1) * 8;
                    int col = nt * 8 + 2 * (l & 3) + (i & 1);
                    stage[h * 2048 + q * 64 + (col ^ ((q & 3) << 3))] = O[mt][nt][i];
                }
    }
    __syncthreads();
    if (s == 0) {
        #pragma unroll
        for (int mt = 0; mt < 2; mt++)
            #pragma unroll
            for (int nt = 0; nt < 8; nt++)
                #pragma unroll
                for (int i = 0; i < 4; i++) {
                    int q = mt * 16 + (l >> 2) + ((i >> 1) & 1) * 8;
                    int col = nt * 8 + 2 * (l & 3) + (i & 1);
                    O[mt][nt][i] += stage[h * 2048 + q * 64 + (col ^ ((q & 3) << 3))];
                }
        #pragma unroll
        for (int mt = 0; mt < 2; mt++)
            #pragma unroll
            for (int nt = 0; nt < 4; nt++)
                #pragma unroll
                for (int i = 0; i < 4; i++)
                    O[mt][nt][i] = __fdividef(O[mt][nt][i], O[mt][nt + 4][i]);
    }
    __syncthreads();
    float* X = (float*)(sm + 8192);       // [32][132]
    if (s == 0) {
        #pragma unroll
        for (int mt = 0; mt < 2; mt++)
            #pragma unroll
            for (int nt = 0; nt < 4; nt++)
                #pragma unroll
                for (int i = 0; i < 4; i++) {
                    int q = mt * 16 + (l >> 2) + ((i >> 1) & 1) * 8;
                    int col = h * 32 + nt * 8 + 2 * (l & 3) + (i & 1);
                    X[q * 132 + col] = O[mt][nt][i];
                }
    }
    __syncthreads();

    const int q = t >> 3, lat0 = (t & 7) * 4;
    float acc[4];
    #pragma unroll
    for (int i = 0; i < 4; i++) acc[i] = bo[lat0 + i];
    #pragma unroll 8
    for (int j = 0; j < 128; j++) {
        float xv = X[q * 132 + j];
        float4 wv = *(const float4*)&Wo[j * 32 + lat0];
        acc[0] += xv * wv.x; acc[1] += xv * wv.y;
        acc[2] += xv * wv.z; acc[3] += xv * wv.w;
    }
    *(float4*)(out + ((long)(b * LQ + qt * 32 + q)) * 32 + lat0) =
        make_float4(acc[0], acc[1], acc[2], acc[3]);
}

// ---------------- launch ------------------------------------------------------
extern "C" void kernel_launch(void* const* d_in, const int* in_sizes, int n_in,
                              void* d_out, int out_size)
{
    const float* query = (const float*)d_in[0];
    const float* key   = (const float*)d_in[1];
    const float* value = (const float*)d_in[2];
    const int*   mask  = (const int*)  d_in[3];
    const float* Wq    = (const float*)d_in[4];
    const float* bq    = (const float*)d_in[5];
    const float* Wk    = (const float*)d_in[6];
    const float* bk    = (const float*)d_in[7];
    const float* Wo    = (const float*)d_in[8];
    const float* bo    = (const float*)d_in[9];
    float* out = (float*)d_out;
    (void)in_sizes; (void)n_in; (void)out_size;

    prep_kernel<<<1600, 256>>>(query, key, value, mask, Wq, bq, Wk, bk);
    dim3 grid(LQ / 32, BB);
    attn_kernel<<<grid, 256>>>(Wo, bo, out);
}